// round 16
// baseline (speedup 1.0000x reference)
#include <cuda_runtime.h>
#include <math.h>

#define BB 16
#define DD 512
#define HH 16
#define HD 32
#define LL 24
#define DFF 2048
#define NQKV 1536
#define TMAX 1024
#define NT 256
#define NCH 2  // attention T-chunks

// attention smem tile geometry
#define TROWS 64
#define RSTRIDE 36               // floats per row (padded)
#define TILEF (TROWS * RSTRIDE)  // 2304 floats per buffer
#define KOFF 368
#define VOFF (368 + 2 * TILEF)
#define ATTN_SMEM (368 + 4 * TILEF)   // 9584 floats

// gemv smem overlay
#define XS_OFF 0            // [128][12] = 1536 floats
#define RED_OFF 1536        // [256][9]  = 2304 floats
#define WSM_OFF 3840        // [DS][32] <= 4096 floats

// ---------------- device scratch ----------------
__device__ float g_h[BB * DD];
__device__ float g_h1[BB * DD];
__device__ float g_pqkv[4 * BB * NQKV];
__device__ float g_po[16 * BB * DD];
__device__ float g_pm1[4 * BB * DFF];
__device__ float g_p2[16 * BB * DD];
__device__ float g_as[BB * HH * NCH];      // per-chunk exp-sum (no-max)
__device__ float g_ao[NCH * BB * HH * HD]; // per-chunk unnormalized V-acc
__device__ unsigned g_bar_count;
__device__ volatile unsigned g_bar_gen;

// ---------------- grid barrier ----------------
__device__ __forceinline__ void gsync() {
    __syncthreads();
    if (threadIdx.x == 0) {
        unsigned gen = g_bar_gen;
        __threadfence();
        if (atomicAdd(&g_bar_count, 1u) == gridDim.x - 1) {
            g_bar_count = 0;
            __threadfence();
            g_bar_gen = gen + 1;
        } else {
            while (g_bar_gen == gen) __nanosleep(64);
            __threadfence();
        }
    }
    __syncthreads();
}

// ---------------- cp.async helpers ----------------
__device__ __forceinline__ void cpa16(unsigned dst, const void* src) {
    asm volatile("cp.async.cg.shared.global [%0], [%1], 16;"
                 :: "r"(dst), "l"(src));
}

// stage weight slice [d0, d0+DS) x [c0, c0+32) into Wsm via cp.async
template <int DS>
__device__ __forceinline__ void stage_w(const float* __restrict__ W, int N,
                                        int d0, int c0, unsigned smw) {
    const int tid = threadIdx.x;
    constexpr int SEGS = DS * 8;  // 16B segments
#pragma unroll
    for (int i = tid; i < SEGS; i += NT) {
        int row = i >> 3, sg = i & 7;
        cpa16(smw + (unsigned)(row * 32 + sg * 4) * 4,
              W + (size_t)(d0 + row) * N + c0 + sg * 4);
    }
    asm volatile("cp.async.commit_group;");
}

// ---------------- preloads (NO trailing sync; overlap with stage_w) -------
template <int DS>
__device__ __forceinline__ void preload_plain(const float* __restrict__ src, int ld,
                                              int d0, int b0, float* xs) {
    const int tid = threadIdx.x;
#pragma unroll
    for (int i = tid; i < DS * 8; i += NT) {
        int bb = i / DS, d = i % DS;
        xs[d * 12 + bb] = src[(size_t)(b0 + bb) * ld + d0 + d];
    }
}

__device__ __forceinline__ void preload_relu(const float* __restrict__ b1,
                                             int d0, int b0, float* xs) {
    const int tid = threadIdx.x;
#pragma unroll
    for (int i = tid; i < 128 * 8; i += NT) {
        int bb = i >> 7, d = i & 127;
        int gd = d0 + d;
        float v = b1[gd];
#pragma unroll
        for (int s = 0; s < 4; s++)
            v += g_pm1[(size_t)(s * BB + b0 + bb) * DFF + gd];
        xs[d * 12 + bb] = fmaxf(v, 0.f);
    }
}

__device__ __forceinline__ void preload_attn(int h, int b0, float* xs) {
    const int tid = threadIdx.x;
    const int bb = tid >> 5, j = tid & 31;
    const int b = b0 + bb;
    const int base = (b * HH + h) * NCH;
    float S = g_as[base + 0] + g_as[base + 1];
    const size_t ob = ((size_t)b * HH + h) * HD + j;
    float o = g_ao[ob] + g_ao[(size_t)BB * HH * HD + ob];
    xs[j * 12 + bb] = o / S;
}

// ---------------- gemv compute: weights from smem ----------------
template <int DS>
__device__ __forceinline__ void gemv_compute(const float* __restrict__ wsm,
                                             float* __restrict__ out, int ldo,
                                             int c0, int b0,
                                             float* xs, float* red) {
    const int tid = threadIdx.x, lane = tid & 31, w = tid >> 5;
    constexpr int DW = DS / 8;
    const float* Wp = wsm + (size_t)(w * DW) * 32 + lane;
    const float* xp = xs + (size_t)(w * DW) * 12;
    float a0 = 0, a1 = 0, a2 = 0, a3 = 0, a4 = 0, a5 = 0, a6 = 0, a7 = 0;
#pragma unroll
    for (int d = 0; d < DW; d++) {
        float wv = Wp[d * 32];
        float4 xa = *(const float4*)(xp + d * 12);
        float4 xb = *(const float4*)(xp + d * 12 + 4);
        a0 += xa.x * wv; a1 += xa.y * wv; a2 += xa.z * wv; a3 += xa.w * wv;
        a4 += xb.x * wv; a5 += xb.y * wv; a6 += xb.z * wv; a7 += xb.w * wv;
    }
    float* rp = red + (size_t)tid * 9;
    rp[0] = a0; rp[1] = a1; rp[2] = a2; rp[3] = a3;
    rp[4] = a4; rp[5] = a5; rp[6] = a6; rp[7] = a7;
    __syncthreads();
    const int cc = tid & 31, bb = tid >> 5;
    float v = 0.f;
#pragma unroll
    for (int w2 = 0; w2 < 8; w2++) v += red[(size_t)(w2 * 32 + cc) * 9 + bb];
    out[(size_t)(b0 + bb) * ldo + c0 + cc] = v;
    __syncthreads();
}

// wait for cp.async weights + preload visibility, in one spot
__device__ __forceinline__ void gemv_join() {
    asm volatile("cp.async.wait_group 0;");
    __syncthreads();
}

// ---------------- attention tile stager (cp.async) ----------------
__device__ __forceinline__ void attn_stage(const float* __restrict__ Kb,
                                           const float* __restrict__ Vb,
                                           int tb, int kv_end, int buf,
                                           unsigned smbase) {
    const int tid = threadIdx.x;
#pragma unroll
    for (int k = 0; k < 4; k++) {
        int seg = tid + k * 256;       // 0..1023
        int isV = seg >> 9;
        int s2 = seg & 511;
        int row = s2 >> 3, dq = s2 & 7;
        int trow = tb + row;
        if (trow < kv_end) {
            const float* src = (isV ? Vb : Kb) + (size_t)trow * HD + dq * 4;
            unsigned dst = smbase +
                ((isV ? VOFF : KOFF) + buf * TILEF + row * RSTRIDE + dq * 4) * 4;
            cpa16(dst, src);
        }
    }
    asm volatile("cp.async.commit_group;");
}

// ---------------- attention chunk: one (b, h, c) --------------------------
__device__ void attn_chunk(const float* __restrict__ Kc, const float* __restrict__ Vc,
                           const float* __restrict__ bq,
                           const int* __restrict__ kvlen,
                           int b, int h, int c, float* sm, unsigned smbase) {
    float* qkv96 = sm;        // [96]
    float* redv  = sm + 96;   // [8][32]
    float* rsum  = sm + 352;  // [8]

    const int tid = threadIdx.x, wid = tid >> 5, lane = tid & 31;
    const int T = kvlen[b];
    const int Ttot = T + 1;
    const int CH = (Ttot + NCH - 1) / NCH;
    const int t0 = c * CH;
    int t1 = t0 + CH; if (t1 > Ttot) t1 = Ttot;
    const float scale = 0.17677669529663687f;

    if (tid < 96) {
        int which = tid >> 5, j = tid & 31;
        int col = which * DD + h * HD + j;
        float v = bq[col];
#pragma unroll
        for (int s = 0; s < 4; s++)
            v += g_pqkv[(size_t)(s * BB + b) * NQKV + col];
        qkv96[which * 32 + j] = v;
    }
    __syncthreads();

    const int outi = (b * HH + h) * NCH + c;
    const size_t ob = ((size_t)b * HH + h) * HD;

    if (t0 >= t1) {
        if (tid == 0) g_as[outi] = 0.f;
        if (tid < HD) g_ao[(size_t)c * BB * HH * HD + ob + tid] = 0.f;
        __syncthreads();
        return;
    }

    const float* Kb = Kc + ((size_t)b * HH + h) * TMAX * HD;
    const float* Vb = Vc + ((size_t)b * HH + h) * TMAX * HD;
    const int kv_end = (t1 < T) ? t1 : T;
    const int len = kv_end - t0;
    const int ntiles = (len + TROWS - 1) / TROWS;

    const int tq = lane >> 3, dq = lane & 7;
    const float4 q4 = *(const float4*)(qkv96 + dq * 4);
    float4 acc = make_float4(0.f, 0.f, 0.f, 0.f);
    float ssum = 0.f;

    if (ntiles > 0) attn_stage(Kb, Vb, t0, kv_end, 0, smbase);
    for (int i = 0; i < ntiles; i++) {
        if (i + 1 < ntiles) {
            attn_stage(Kb, Vb, t0 + (i + 1) * TROWS, kv_end, (i + 1) & 1, smbase);
            asm volatile("cp.async.wait_group 1;");
        } else {
            asm volatile("cp.async.wait_group 0;");
        }
        __syncthreads();
        const float* Kt = sm + KOFF + (i & 1) * TILEF;
        const float* Vt = sm + VOFF + (i & 1) * TILEF;
        const int tb = t0 + i * TROWS;
#pragma unroll
        for (int j = 0; j < 2; j++) {
            int row = wid * 8 + j * 4 + tq;
            bool valid = (tb + row) < kv_end;
            float4 k4 = *(const float4*)(Kt + row * RSTRIDE + dq * 4);
            float s = k4.x * q4.x + k4.y * q4.y + k4.z * q4.z + k4.w * q4.w;
            s += __shfl_xor_sync(0xffffffffu, s, 1);
            s += __shfl_xor_sync(0xffffffffu, s, 2);
            s += __shfl_xor_sync(0xffffffffu, s, 4);
            float e = valid ? __expf(s * scale) : 0.f;
            float4 v4 = *(const float4*)(Vt + row * RSTRIDE + dq * 4);
            ssum += e;
            acc.x += e * v4.x; acc.y += e * v4.y;
            acc.z += e * v4.z; acc.w += e * v4.w;
        }
        __syncthreads();
    }

    if (t1 > T && wid == 0) {  // new token at position T
        const float* kns = qkv96 + 32;
        const float* vns = qkv96 + 64;
        float4 k4 = *(const float4*)(kns + dq * 4);
        float s = k4.x * q4.x + k4.y * q4.y + k4.z * q4.z + k4.w * q4.w;
        s += __shfl_xor_sync(0xffffffffu, s, 1);
        s += __shfl_xor_sync(0xffffffffu, s, 2);
        s += __shfl_xor_sync(0xffffffffu, s, 4);
        float e = (tq == 0) ? __expf(s * scale) : 0.f;
        float4 v4 = *(const float4*)(vns + dq * 4);
        ssum += e;
        acc.x += e * v4.x; acc.y += e * v4.y;
        acc.z += e * v4.z; acc.w += e * v4.w;
    }

#pragma unroll
    for (int o = 8; o <= 16; o <<= 1) {
        acc.x += __shfl_xor_sync(0xffffffffu, acc.x, o);
        acc.y += __shfl_xor_sync(0xffffffffu, acc.y, o);
        acc.z += __shfl_xor_sync(0xffffffffu, acc.z, o);
        acc.w += __shfl_xor_sync(0xffffffffu, acc.w, o);
    }
#pragma unroll
    for (int o = 16; o; o >>= 1) ssum += __shfl_xor_sync(0xffffffffu, ssum, o);
    if (tq == 0) *(float4*)(redv + wid * 32 + dq * 4) = acc;
    if (lane == 0) rsum[wid] = ssum;
    __syncthreads();
    if (tid < HD) {
        float o = 0.f;
#pragma unroll
        for (int w = 0; w < 8; w++) o += redv[w * 32 + tid];
        g_ao[(size_t)c * BB * HH * HD + ob + tid] = o;
    }
    if (tid == 0) {
        float ss = 0.f;
#pragma unroll
        for (int w = 0; w < 8; w++) ss += rsum[w];
        g_as[outi] = ss * 0.125f;
    }
    __syncthreads();
}

// ---------------- LN stage ----------------
template <int S>
__device__ void ln_stage(const float* __restrict__ part,
                         const float* __restrict__ resid,
                         const float* __restrict__ bias,
                         const float* __restrict__ gam,
                         const float* __restrict__ bet,
                         float* __restrict__ out, int b, float* sm) {
    const int tid = threadIdx.x, lane = tid & 31, wid = tid >> 5;
    float v0, v1;
    {
        int j = tid;
        float t = resid[(size_t)b * DD + j] + bias[j];
#pragma unroll
        for (int s = 0; s < S; s++) t += part[(size_t)(s * BB + b) * DD + j];
        v0 = t;
        j = tid + 256;
        t = resid[(size_t)b * DD + j] + bias[j];
#pragma unroll
        for (int s = 0; s < S; s++) t += part[(size_t)(s * BB + b) * DD + j];
        v1 = t;
    }
    float s1 = v0 + v1, s2 = v0 * v0 + v1 * v1;
#pragma unroll
    for (int o = 16; o; o >>= 1) {
        s1 += __shfl_xor_sync(0xffffffffu, s1, o);
        s2 += __shfl_xor_sync(0xffffffffu, s2, o);
    }
    float* rs = sm; float* rq = sm + 8; float* mv = sm + 16;
    if (lane == 0) { rs[wid] = s1; rq[wid] = s2; }
    __syncthreads();
    if (tid == 0) {
        float a = 0.f, q = 0.f;
#pragma unroll
        for (int w = 0; w < 8; w++) { a += rs[w]; q += rq[w]; }
        float mean = a / DD;
        mv[0] = mean;
        mv[1] = rsqrtf(q / DD - mean * mean + 1e-5f);
    }
    __syncthreads();
    const float mean = mv[0], rstd = mv[1];
    out[(size_t)b * DD + tid] = (v0 - mean) * rstd * gam[tid] + bet[tid];
    out[(size_t)b * DD + tid + 256] =
        (v1 - mean) * rstd * gam[tid + 256] + bet[tid + 256];
    __syncthreads();
}

// ---------------- persistent kernel ----------------
__global__ void __launch_bounds__(NT, 4)
decoder_kernel(const float* __restrict__ x,
               const float* __restrict__ kc, const float* __restrict__ vc,
               const float* __restrict__ ln1g, const float* __restrict__ ln1b,
               const float* __restrict__ qkvw, const float* __restrict__ qkvb,
               const float* __restrict__ outw, const float* __restrict__ outb,
               const float* __restrict__ ln2g, const float* __restrict__ ln2b,
               const float* __restrict__ w1, const float* __restrict__ b1,
               const float* __restrict__ w2, const float* __restrict__ b2,
               const int* __restrict__ kvlen, float* __restrict__ dout) {
    extern __shared__ float sm[];
    float* xs  = sm + XS_OFF;
    float* red = sm + RED_OFF;
    float* wsm = sm + WSM_OFF;
    const unsigned smbase = (unsigned)__cvta_generic_to_shared(sm);
    const unsigned smw = smbase + WSM_OFF * 4;

    for (int l = 0; l < LL; l++) {
        const float* Wq = qkvw + (size_t)l * DD * NQKV;
        const float* bq = qkvb + (size_t)l * NQKV;
        const float* Wo = outw + (size_t)l * DD * DD;
        const float* bo = outb + (size_t)l * DD;
        const float* W1 = w1 + (size_t)l * DD * DFF;
        const float* B1 = b1 + (size_t)l * DFF;
        const float* W2 = w2 + (size_t)l * DFF * DD;
        const float* Kc = kc + (size_t)l * BB * HH * TMAX * HD;
        const float* Vc = vc + (size_t)l * BB * HH * TMAX * HD;

        // S0: produce g_h (x for l==0, else LN2 of prev). 16 vblocks.
        if (l == 0) {
            for (int i = blockIdx.x * NT + threadIdx.x; i < BB * DD;
                 i += gridDim.x * NT)
                g_h[i] = x[i];
        } else {
            for (int vb = blockIdx.x; vb < 16; vb += gridDim.x)
                ln_stage<16>(g_p2, g_h1, b2 + (size_t)(l - 1) * DD,
                             ln2g + (size_t)(l - 1) * DD,
                             ln2b + (size_t)(l - 1) * DD, g_h, vb, sm);
        }
        gsync();

        // S1: qkv split-K4 (DS=128). W via cp.async overlapped with x preload.
        for (int vb = blockIdx.x; vb < 384; vb += gridDim.x) {
            int ks = vb & 3, b0 = ((vb >> 2) & 1) * 8, c0 = (vb >> 3) * 32;
            stage_w<128>(Wq, NQKV, ks * 128, c0, smw);
            preload_plain<128>(g_h, DD, ks * 128, b0, xs);
            gemv_join();
            gemv_compute<128>(wsm, g_pqkv + (size_t)ks * BB * NQKV, NQKV,
                              c0, b0, xs, red);
        }
        gsync();

        // S2: attention T-split 2, cp.async pipelined. 512 vblocks.
        for (int vb = blockIdx.x; vb < 512; vb += gridDim.x) {
            int c = vb & 1, h = (vb >> 1) & 15, b = vb >> 5;
            attn_chunk(Kc, Vc, bq, kvlen, b, h, c, sm, smbase);
        }
        gsync();

        // S3: outproj split-K16 (DS=32), sum-merge in preload. 512 vblocks.
        for (int vb = blockIdx.x; vb < 512; vb += gridDim.x) {
            int ks = vb & 15, b0 = ((vb >> 4) & 1) * 8, c0 = (vb >> 5) * 32;
            stage_w<32>(Wo, DD, ks * 32, c0, smw);
            preload_attn(ks, b0, xs);  // h == ks since DS == HD
            gemv_join();
            gemv_compute<32>(wsm, g_po + (size_t)ks * BB * DD, DD,
                             c0, b0, xs, red);
        }
        gsync();

        // S4: LN1 (merge 16 outproj partials + residual + bo). 16 vblocks.
        for (int vb = blockIdx.x; vb < 16; vb += gridDim.x)
            ln_stage<16>(g_po, g_h, bo, ln1g + (size_t)l * DD,
                         ln1b + (size_t)l * DD, g_h1, vb, sm);
        gsync();

        // S5: mlp1 split-K4 (DS=128). 512 vblocks.
        for (int vb = blockIdx.x; vb < 512; vb += gridDim.x) {
            int ks = vb & 3, b0 = ((vb >> 2) & 1) * 8, c0 = (vb >> 3) * 32;
            stage_w<128>(W1, DFF, ks * 128, c0, smw);
            preload_plain<128>(g_h1, DD, ks * 128, b0, xs);
            gemv_join();
            gemv_compute<128>(wsm, g_pm1 + (size_t)ks * BB * DFF, DFF,
                              c0, b0, xs, red);
        }
        gsync();

        // S6: mlp2 split-K16 (DS=128), relu+merge in preload. 512 vblocks.
        for (int vb = blockIdx.x; vb < 512; vb += gridDim.x) {
            int ks = vb & 15, b0 = ((vb >> 4) & 1) * 8, c0 = (vb >> 5) * 32;
            stage_w<128>(W2, DD, ks * 128, c0, smw);
            preload_relu(B1, ks * 128, b0, xs);
            gemv_join();
            gemv_compute<128>(wsm, g_p2 + (size_t)ks * BB * DD, DD,
                              c0, b0, xs, red);
        }
        gsync();
    }

    // final: LN2 of last layer -> d_out. 16 vblocks.
    for (int vb = blockIdx.x; vb < 16; vb += gridDim.x)
        ln_stage<16>(g_p2, g_h1, b2 + (size_t)(LL - 1) * DD,
                     ln2g + (size_t)(LL - 1) * DD,
                     ln2b + (size_t)(LL - 1) * DD, dout, vb, sm);
}

// ---------------- launcher ----------------
extern "C" void kernel_launch(void* const* d_in, const int* in_sizes, int n_in,
                              void* d_out, int out_size) {
    (void)in_sizes; (void)n_in; (void)out_size;
    const float* x    = (const float*)d_in[0];
    const float* kc   = (const float*)d_in[1];
    const float* vc   = (const float*)d_in[2];
    const float* ln1g = (const float*)d_in[3];
    const float* ln1b = (const float*)d_in[4];
    const float* qkvw = (const float*)d_in[5];
    const float* qkvb = (const float*)d_in[6];
    const float* outw = (const float*)d_in[7];
    const float* outb = (const float*)d_in[8];
    const float* ln2g = (const float*)d_in[9];
    const float* ln2b = (const float*)d_in[10];
    const float* w1   = (const float*)d_in[11];
    const float* b1   = (const float*)d_in[12];
    const float* w2   = (const float*)d_in[13];
    const float* b2   = (const float*)d_in[14];
    const int* kvlen  = (const int*)d_in[16];

    static int grid = 0;
    const int SMEM = ATTN_SMEM * 4;  // 38336 B (covers gemv overlay 31744 B)
    if (!grid) {
        cudaFuncSetAttribute(decoder_kernel,
                             cudaFuncAttributeMaxDynamicSharedMemorySize, SMEM);
        int dev = 0;
        cudaGetDevice(&dev);
        cudaDeviceProp prop;
        cudaGetDeviceProperties(&prop, dev);
        int occ = 0;
        cudaOccupancyMaxActiveBlocksPerMultiprocessor(&occ, decoder_kernel,
                                                      NT, SMEM);
        if (occ < 1) occ = 1;
        if (occ > 4) occ = 4;
        grid = prop.multiProcessorCount * occ;
    }

    decoder_kernel<<<grid, NT, SMEM>>>(
        x, kc, vc, ln1g, ln1b, qkvw, qkvb, outw, outb, ln2g, ln2b,
        w1, b1, w2, b2, kvlen, (float*)d_out);
}